// round 1
// baseline (speedup 1.0000x reference)
#include <cuda_runtime.h>
#include <cuda_bf16.h>

// Problem constants
#define BB 32
#define SS 4096
#define DD 256
#define DA 128
#define DP 64

#define NCHUNK 32            // S-chunks per batch
#define SPC (SS / NCHUNK)    // 128 s-rows per block
#define NWARP 8
#define SPW (SPC / NWARP)    // 16 s-rows per warp

// Scratch (allocation-free rule: __device__ globals)
__device__ float g_va[DD];
__device__ float g_vp1[DP];
__device__ float g_vp2[DP];
__device__ float g_cq[BB];                    // per-batch q-term + bias
__device__ float g_pl[BB * NCHUNK];           // partial sum of exp
__device__ float g_pacc[BB * NCHUNK * DD];    // partial weighted h sums

// ---------------------------------------------------------------------------
// Kernel 0: fold Wc into vectors; per-batch scalar cq[b] = q[b]·(Wq^T wq) + bc
// ---------------------------------------------------------------------------
__global__ void prep_kernel(const float* __restrict__ q,
                            const float* __restrict__ Wh,
                            const float* __restrict__ Wq,
                            const float* __restrict__ Wp1,
                            const float* __restrict__ Wp2,
                            const float* __restrict__ Wc,
                            const float* __restrict__ bc) {
    __shared__ float s_wqv[DD];
    int t = threadIdx.x;                 // 256 threads
    float va = 0.f, wqv = 0.f;
    #pragma unroll 4
    for (int a = 0; a < DA; a++) {
        va  += Wh[a * DD + t] * Wc[a];
        wqv += Wq[a * DD + t] * Wc[DA + a];
    }
    g_va[t]  = va;
    s_wqv[t] = wqv;
    if (t < DP) {
        float v1 = 0.f, v2 = 0.f;
        #pragma unroll 4
        for (int a = 0; a < DP; a++) {
            v1 += Wp1[a * DP + t] * Wc[2 * DA + a];
            v2 += Wp2[a * DP + t] * Wc[2 * DA + DP + a];
        }
        g_vp1[t] = v1;
        g_vp2[t] = v2;
    }
    __syncthreads();
    int w = t >> 5, lane = t & 31;
    for (int b = w; b < BB; b += NWARP) {
        float s = 0.f;
        #pragma unroll
        for (int d = lane; d < DD; d += 32) s += q[b * DD + d] * s_wqv[d];
        #pragma unroll
        for (int off = 16; off; off >>= 1) s += __shfl_xor_sync(0xffffffffu, s, off);
        if (lane == 0) g_cq[b] = s + bc[0];
    }
}

// ---------------------------------------------------------------------------
// Kernel 1: fused score + tanh + exp + weighted accumulation, single h pass.
// Grid: (NCHUNK, B). Block: 256 threads = 8 warps; each warp owns SPW s-rows.
// Lane l owns h dims [8l,8l+8) and pf dims [2l,2l+2).
// ---------------------------------------------------------------------------
__global__ void __launch_bounds__(256, 4)
score_kernel(const float* __restrict__ h,
             const float* __restrict__ pf1,
             const float* __restrict__ pf2) {
    const int b     = blockIdx.y;
    const int chunk = blockIdx.x;
    const int w     = threadIdx.x >> 5;
    const int lane  = threadIdx.x & 31;

    // Per-lane cached projection-vector slices
    const float4 va0 = *(const float4*)(g_va + lane * 8);
    const float4 va1 = *(const float4*)(g_va + lane * 8 + 4);
    const float2 w1  = *(const float2*)(g_vp1 + lane * 2);
    const float2 w2  = *(const float2*)(g_vp2 + lane * 2);
    const float  cqb = g_cq[b];

    const int s0 = chunk * SPC + w * SPW;
    const float* hp = h   + ((size_t)b * SS + s0) * DD + lane * 8;
    const float* p1 = pf1 + ((size_t)b * SS + s0) * DP + lane * 2;
    const float* p2 = pf2 + ((size_t)b * SS + s0) * DP + lane * 2;

    float l = 0.f;
    float a0 = 0.f, a1 = 0.f, a2 = 0.f, a3 = 0.f;
    float a4 = 0.f, a5 = 0.f, a6 = 0.f, a7 = 0.f;

    #pragma unroll 4
    for (int i = 0; i < SPW; i++) {
        const float4 h0 = *(const float4*)(hp);
        const float4 h1 = *(const float4*)(hp + 4);
        const float2 f1 = *(const float2*)(p1);
        const float2 f2 = *(const float2*)(p2);
        hp += DD; p1 += DP; p2 += DP;

        float part = h0.x * va0.x + h0.y * va0.y + h0.z * va0.z + h0.w * va0.w
                   + h1.x * va1.x + h1.y * va1.y + h1.z * va1.z + h1.w * va1.w
                   + f1.x * w1.x  + f1.y * w1.y
                   + f2.x * w2.x  + f2.y * w2.y;
        #pragma unroll
        for (int off = 16; off; off >>= 1)
            part += __shfl_xor_sync(0xffffffffu, part, off);

        // tanh is bounded -> exp is always safe, no running max needed
        const float wgt = __expf(tanhf(part + cqb));
        l  += wgt;
        a0 += wgt * h0.x;  a1 += wgt * h0.y;  a2 += wgt * h0.z;  a3 += wgt * h0.w;
        a4 += wgt * h1.x;  a5 += wgt * h1.y;  a6 += wgt * h1.z;  a7 += wgt * h1.w;
    }

    // Block-level combine of 8 warp partials
    __shared__ float s_acc[NWARP][DD];
    __shared__ float s_l[NWARP];
    float* dst = &s_acc[w][lane * 8];
    dst[0] = a0; dst[1] = a1; dst[2] = a2; dst[3] = a3;
    dst[4] = a4; dst[5] = a5; dst[6] = a6; dst[7] = a7;
    if (lane == 0) s_l[w] = l;
    __syncthreads();

    const int t = threadIdx.x;        // t in [0,256): one output dim each
    float accd = 0.f;
    #pragma unroll
    for (int ww = 0; ww < NWARP; ww++) accd += s_acc[ww][t];
    const int pidx = b * NCHUNK + chunk;
    g_pacc[(size_t)pidx * DD + t] = accd;
    if (t == 0) {
        float L = 0.f;
        #pragma unroll
        for (int ww = 0; ww < NWARP; ww++) L += s_l[ww];
        g_pl[pidx] = L;
    }
}

// ---------------------------------------------------------------------------
// Kernel 2: combine partials -> context[b,d] = sum(acc) / (sum(l) * S)
// ---------------------------------------------------------------------------
__global__ void finalize_kernel(float* __restrict__ out) {
    const int b = blockIdx.x;
    const int t = threadIdx.x;        // 256 threads, one d each
    float L = 0.f;
    #pragma unroll
    for (int k = 0; k < NCHUNK; k++) L += g_pl[b * NCHUNK + k];
    float acc = 0.f;
    #pragma unroll 8
    for (int k = 0; k < NCHUNK; k++)
        acc += g_pacc[((size_t)b * NCHUNK + k) * DD + t];
    out[b * DD + t] = acc / (L * (float)SS);
}

// ---------------------------------------------------------------------------
extern "C" void kernel_launch(void* const* d_in, const int* in_sizes, int n_in,
                              void* d_out, int out_size) {
    const float* h   = (const float*)d_in[0];
    const float* q   = (const float*)d_in[1];
    const float* pf1 = (const float*)d_in[2];
    const float* pf2 = (const float*)d_in[3];
    const float* Wh  = (const float*)d_in[4];
    const float* Wq  = (const float*)d_in[5];
    const float* Wp1 = (const float*)d_in[6];
    const float* Wp2 = (const float*)d_in[7];
    const float* Wc  = (const float*)d_in[8];
    const float* bc  = (const float*)d_in[9];
    float* out = (float*)d_out;

    prep_kernel<<<1, 256>>>(q, Wh, Wq, Wp1, Wp2, Wc, bc);
    score_kernel<<<dim3(NCHUNK, BB), 256>>>(h, pf1, pf2);
    finalize_kernel<<<BB, 256>>>(out);
}

// round 6
// speedup vs baseline: 1.6861x; 1.6861x over previous
#include <cuda_runtime.h>
#include <cuda_bf16.h>

// Problem constants
#define BB 32
#define SS 4096
#define DD 256
#define DA 128
#define DP 64

#define NCHUNK 32            // S-chunks per batch
#define SPC (SS / NCHUNK)    // 128 s-rows per block
#define NWARP 8
#define SPW (SPC / NWARP)    // 16 s-rows per warp

// Scratch (allocation-free rule: __device__ globals)
__device__ float g_va[DD];
__device__ float g_wqv[DD];
__device__ float g_vp1[DP];
__device__ float g_vp2[DP];
__device__ float g_pl[BB * NCHUNK];           // partial sum of exp
__device__ float g_pacc[BB * NCHUNK * DD];    // partial weighted h sums

// ---------------------------------------------------------------------------
// Kernel 0 (fully parallel, depth-1): fold Wc into projection vectors.
// 40 blocks, each computes a 16-element slice of one output vector:
//   blocks  0..15 : g_va  [t0=16j], reduce over a=0..127 of Wh
//   blocks 16..31 : g_wqv [t0=16j], reduce over a=0..127 of Wq
//   blocks 32..35 : g_vp1 [t0=16j], reduce over a=0..63  of Wp1
//   blocks 36..39 : g_vp2 [t0=16j], reduce over a=0..63  of Wp2
// Thread layout: t = tl (0..15, output index) + 16*ag (0..15, a-group).
// ---------------------------------------------------------------------------
__global__ void prep_kernel(const float* __restrict__ Wh,
                            const float* __restrict__ Wq,
                            const float* __restrict__ Wp1,
                            const float* __restrict__ Wp2,
                            const float* __restrict__ Wc) {
    __shared__ float red[256];
    const int blk = blockIdx.x;
    const int t   = threadIdx.x;
    const int tl  = t & 15;
    const int ag  = t >> 4;        // 0..15

    float acc = 0.f;
    float* out;
    int t0;

    if (blk < 32) {
        const float* W    = (blk < 16) ? Wh : Wq;
        const float* wvec = (blk < 16) ? Wc : (Wc + DA);
        out = (blk < 16) ? g_va : g_wqv;
        t0  = (blk & 15) * 16;
        #pragma unroll
        for (int k = 0; k < 8; k++) {
            int a = ag + k * 16;                       // a covers 0..127
            acc += W[a * DD + t0 + tl] * wvec[a];
        }
    } else {
        const float* W    = (blk < 36) ? Wp1 : Wp2;
        const float* wvec = (blk < 36) ? (Wc + 2 * DA) : (Wc + 2 * DA + DP);
        out = (blk < 36) ? g_vp1 : g_vp2;
        t0  = (blk & 3) * 16;
        #pragma unroll
        for (int k = 0; k < 4; k++) {
            int a = ag + k * 16;                       // a covers 0..63
            acc += W[a * DP + t0 + tl] * wvec[a];
        }
    }

    red[t] = acc;
    __syncthreads();
    if (t < 16) {
        float s = 0.f;
        #pragma unroll
        for (int g = 0; g < 16; g++) s += red[g * 16 + t];
        out[t0 + t] = s;
    }
}

// ---------------------------------------------------------------------------
// Kernel 1: fused score + tanh + exp + weighted accumulation, single h pass.
// Grid: (NCHUNK, B). Block: 256 threads = 8 warps; each warp owns SPW s-rows.
// Lane l owns h dims [8l,8l+8) and pf dims [2l,2l+2).
// The per-batch scalar cq[b] = q[b]·wqv + bc is computed in-block (L2 hits).
// ---------------------------------------------------------------------------
__global__ void __launch_bounds__(256, 4)
score_kernel(const float* __restrict__ h,
             const float* __restrict__ pf1,
             const float* __restrict__ pf2,
             const float* __restrict__ q,
             const float* __restrict__ bc) {
    const int b     = blockIdx.y;
    const int chunk = blockIdx.x;
    const int t     = threadIdx.x;
    const int w     = t >> 5;
    const int lane  = t & 31;

    __shared__ float s_red[NWARP];

    // In-block cq[b] = q[b] . wqv  (all reads L2-resident; overlapped cost ~0)
    {
        float p = g_wqv[t] * q[b * DD + t];
        #pragma unroll
        for (int off = 16; off; off >>= 1)
            p += __shfl_xor_sync(0xffffffffu, p, off);
        if (lane == 0) s_red[w] = p;
    }

    // Per-lane cached projection-vector slices
    const float4 va0 = *(const float4*)(g_va + lane * 8);
    const float4 va1 = *(const float4*)(g_va + lane * 8 + 4);
    const float2 w1  = *(const float2*)(g_vp1 + lane * 2);
    const float2 w2  = *(const float2*)(g_vp2 + lane * 2);

    __syncthreads();
    float cqb = bc[0];
    #pragma unroll
    for (int ww = 0; ww < NWARP; ww++) cqb += s_red[ww];

    const int s0 = chunk * SPC + w * SPW;
    const float* hp = h   + ((size_t)b * SS + s0) * DD + lane * 8;
    const float* p1 = pf1 + ((size_t)b * SS + s0) * DP + lane * 2;
    const float* p2 = pf2 + ((size_t)b * SS + s0) * DP + lane * 2;

    float l = 0.f;
    float a0 = 0.f, a1 = 0.f, a2 = 0.f, a3 = 0.f;
    float a4 = 0.f, a5 = 0.f, a6 = 0.f, a7 = 0.f;

    #pragma unroll 8
    for (int i = 0; i < SPW; i++) {
        const float4 h0 = *(const float4*)(hp);
        const float4 h1 = *(const float4*)(hp + 4);
        const float2 f1 = *(const float2*)(p1);
        const float2 f2 = *(const float2*)(p2);
        hp += DD; p1 += DP; p2 += DP;

        float part = h0.x * va0.x + h0.y * va0.y + h0.z * va0.z + h0.w * va0.w
                   + h1.x * va1.x + h1.y * va1.y + h1.z * va1.z + h1.w * va1.w
                   + f1.x * w1.x  + f1.y * w1.y
                   + f2.x * w2.x  + f2.y * w2.y;
        #pragma unroll
        for (int off = 16; off; off >>= 1)
            part += __shfl_xor_sync(0xffffffffu, part, off);

        // tanh is bounded -> exp is always safe, no running max needed
        const float wgt = __expf(tanhf(part + cqb));
        l  += wgt;
        a0 += wgt * h0.x;  a1 += wgt * h0.y;  a2 += wgt * h0.z;  a3 += wgt * h0.w;
        a4 += wgt * h1.x;  a5 += wgt * h1.y;  a6 += wgt * h1.z;  a7 += wgt * h1.w;
    }

    // Block-level combine of 8 warp partials
    __shared__ float s_acc[NWARP][DD];
    __shared__ float s_l[NWARP];
    float* dst = &s_acc[w][lane * 8];
    dst[0] = a0; dst[1] = a1; dst[2] = a2; dst[3] = a3;
    dst[4] = a4; dst[5] = a5; dst[6] = a6; dst[7] = a7;
    if (lane == 0) s_l[w] = l;
    __syncthreads();

    float accd = 0.f;
    #pragma unroll
    for (int ww = 0; ww < NWARP; ww++) accd += s_acc[ww][t];
    const int pidx = b * NCHUNK + chunk;
    g_pacc[(size_t)pidx * DD + t] = accd;
    if (t == 0) {
        float L = 0.f;
        #pragma unroll
        for (int ww = 0; ww < NWARP; ww++) L += s_l[ww];
        g_pl[pidx] = L;
    }
}

// ---------------------------------------------------------------------------
// Kernel 2: combine partials -> context[b,d] = sum(acc) / (sum(l) * S)
// ---------------------------------------------------------------------------
__global__ void finalize_kernel(float* __restrict__ out) {
    const int b = blockIdx.x;
    const int t = threadIdx.x;        // 256 threads, one d each
    float L = 0.f;
    #pragma unroll
    for (int k = 0; k < NCHUNK; k++) L += g_pl[b * NCHUNK + k];
    float acc = 0.f;
    #pragma unroll 8
    for (int k = 0; k < NCHUNK; k++)
        acc += g_pacc[((size_t)b * NCHUNK + k) * DD + t];
    out[b * DD + t] = acc / (L * (float)SS);
}

// ---------------------------------------------------------------------------
extern "C" void kernel_launch(void* const* d_in, const int* in_sizes, int n_in,
                              void* d_out, int out_size) {
    const float* h   = (const float*)d_in[0];
    const float* q   = (const float*)d_in[1];
    const float* pf1 = (const float*)d_in[2];
    const float* pf2 = (const float*)d_in[3];
    const float* Wh  = (const float*)d_in[4];
    const float* Wq  = (const float*)d_in[5];
    const float* Wp1 = (const float*)d_in[6];
    const float* Wp2 = (const float*)d_in[7];
    const float* Wc  = (const float*)d_in[8];
    const float* bc  = (const float*)d_in[9];
    float* out = (float*)d_out;

    prep_kernel<<<40, 256>>>(Wh, Wq, Wp1, Wp2, Wc);
    score_kernel<<<dim3(NCHUNK, BB), 256>>>(h, pf1, pf2, q, bc);
    finalize_kernel<<<BB, 256>>>(out);
}

// round 8
// speedup vs baseline: 1.7675x; 1.0482x over previous
#include <cuda_runtime.h>
#include <cuda_bf16.h>

// Problem constants
#define BB 32
#define SS 4096
#define DD 256
#define DA 128
#define DP 64

#define NCHUNK 16            // S-chunks per batch -> grid 512 = single wave @ occ 4
#define SPC (SS / NCHUNK)    // 256 s-rows per block
#define NWARP 8
#define SPW (SPC / NWARP)    // 32 s-rows per warp

// Scratch (allocation-free rule: __device__ globals)
__device__ float g_va[DD];
__device__ float g_wqv[DD];
__device__ float g_vp1[DP];
__device__ float g_vp2[DP];
__device__ float g_pl[BB * NCHUNK];           // partial sum of exp
__device__ float g_pacc[BB * NCHUNK * DD];    // partial weighted h sums
__device__ unsigned int g_cnt[BB];            // per-batch completion counters

// ---------------------------------------------------------------------------
// Kernel 0 (fully parallel, depth-1): fold Wc into projection vectors,
// and reset the per-batch completion counters for this replay.
// 40 blocks, each computes a 16-element slice of one output vector.
// ---------------------------------------------------------------------------
__global__ void prep_kernel(const float* __restrict__ Wh,
                            const float* __restrict__ Wq,
                            const float* __restrict__ Wp1,
                            const float* __restrict__ Wp2,
                            const float* __restrict__ Wc) {
    __shared__ float red[256];
    const int blk = blockIdx.x;
    const int t   = threadIdx.x;
    const int tl  = t & 15;
    const int ag  = t >> 4;        // 0..15

    if (blk == 0 && t < BB) g_cnt[t] = 0u;   // graph-replay-safe counter reset

    float acc = 0.f;
    float* out;
    int t0;

    if (blk < 32) {
        const float* W    = (blk < 16) ? Wh : Wq;
        const float* wvec = (blk < 16) ? Wc : (Wc + DA);
        out = (blk < 16) ? g_va : g_wqv;
        t0  = (blk & 15) * 16;
        #pragma unroll
        for (int k = 0; k < 8; k++) {
            int a = ag + k * 16;                       // a covers 0..127
            acc += W[a * DD + t0 + tl] * wvec[a];
        }
    } else {
        const float* W    = (blk < 36) ? Wp1 : Wp2;
        const float* wvec = (blk < 36) ? (Wc + 2 * DA) : (Wc + 2 * DA + DP);
        out = (blk < 36) ? g_vp1 : g_vp2;
        t0  = (blk & 3) * 16;
        #pragma unroll
        for (int k = 0; k < 4; k++) {
            int a = ag + k * 16;                       // a covers 0..63
            acc += W[a * DP + t0 + tl] * wvec[a];
        }
    }

    red[t] = acc;
    __syncthreads();
    if (t < 16) {
        float s = 0.f;
        #pragma unroll
        for (int g = 0; g < 16; g++) s += red[g * 16 + t];
        out[t0 + t] = s;
    }
}

// ---------------------------------------------------------------------------
// Kernel 1: fused score + tanh + exp + weighted accumulation, single h pass,
// with the finalize folded in: the last-finishing block of each batch reduces
// the NCHUNK partials (L2-resident) and writes the output row.
// Grid: (NCHUNK, B). Block: 256 threads = 8 warps; each warp owns SPW s-rows.
// Lane l owns h dims [8l,8l+8) and pf dims [2l,2l+2).
// ---------------------------------------------------------------------------
__global__ void __launch_bounds__(256, 4)
score_kernel(const float* __restrict__ h,
             const float* __restrict__ pf1,
             const float* __restrict__ pf2,
             const float* __restrict__ q,
             const float* __restrict__ bc,
             float* __restrict__ outp) {
    const int b     = blockIdx.y;
    const int chunk = blockIdx.x;
    const int t     = threadIdx.x;
    const int w     = t >> 5;
    const int lane  = t & 31;

    __shared__ float s_red[NWARP];

    // In-block cq[b] = q[b] . wqv  (all reads L2-resident; overlapped cost ~0)
    {
        float p = g_wqv[t] * q[b * DD + t];
        #pragma unroll
        for (int off = 16; off; off >>= 1)
            p += __shfl_xor_sync(0xffffffffu, p, off);
        if (lane == 0) s_red[w] = p;
    }

    // Per-lane cached projection-vector slices
    const float4 va0 = *(const float4*)(g_va + lane * 8);
    const float4 va1 = *(const float4*)(g_va + lane * 8 + 4);
    const float2 w1  = *(const float2*)(g_vp1 + lane * 2);
    const float2 w2  = *(const float2*)(g_vp2 + lane * 2);

    __syncthreads();
    float cqb = bc[0];
    #pragma unroll
    for (int ww = 0; ww < NWARP; ww++) cqb += s_red[ww];

    const int s0 = chunk * SPC + w * SPW;
    const float* hp = h   + ((size_t)b * SS + s0) * DD + lane * 8;
    const float* p1 = pf1 + ((size_t)b * SS + s0) * DP + lane * 2;
    const float* p2 = pf2 + ((size_t)b * SS + s0) * DP + lane * 2;

    float l = 0.f;
    float a0 = 0.f, a1 = 0.f, a2 = 0.f, a3 = 0.f;
    float a4 = 0.f, a5 = 0.f, a6 = 0.f, a7 = 0.f;

    #pragma unroll 8
    for (int i = 0; i < SPW; i++) {
        const float4 h0 = *(const float4*)(hp);
        const float4 h1 = *(const float4*)(hp + 4);
        const float2 f1 = *(const float2*)(p1);
        const float2 f2 = *(const float2*)(p2);
        hp += DD; p1 += DP; p2 += DP;

        float part = h0.x * va0.x + h0.y * va0.y + h0.z * va0.z + h0.w * va0.w
                   + h1.x * va1.x + h1.y * va1.y + h1.z * va1.z + h1.w * va1.w
                   + f1.x * w1.x  + f1.y * w1.y
                   + f2.x * w2.x  + f2.y * w2.y;
        #pragma unroll
        for (int off = 16; off; off >>= 1)
            part += __shfl_xor_sync(0xffffffffu, part, off);

        // tanh is bounded -> exp is always safe, no running max needed
        const float wgt = __expf(tanhf(part + cqb));
        l  += wgt;
        a0 += wgt * h0.x;  a1 += wgt * h0.y;  a2 += wgt * h0.z;  a3 += wgt * h0.w;
        a4 += wgt * h1.x;  a5 += wgt * h1.y;  a6 += wgt * h1.z;  a7 += wgt * h1.w;
    }

    // Block-level combine of 8 warp partials
    __shared__ float s_acc[NWARP][DD];
    __shared__ float s_l[NWARP];
    float* dst = &s_acc[w][lane * 8];
    dst[0] = a0; dst[1] = a1; dst[2] = a2; dst[3] = a3;
    dst[4] = a4; dst[5] = a5; dst[6] = a6; dst[7] = a7;
    if (lane == 0) s_l[w] = l;
    __syncthreads();

    float accd = 0.f;
    #pragma unroll
    for (int ww = 0; ww < NWARP; ww++) accd += s_acc[ww][t];
    const int pidx = b * NCHUNK + chunk;
    g_pacc[(size_t)pidx * DD + t] = accd;
    if (t == 0) {
        float L = 0.f;
        #pragma unroll
        for (int ww = 0; ww < NWARP; ww++) L += s_l[ww];
        g_pl[pidx] = L;
    }

    // ---- inlined finalize: last block of this batch combines the partials --
    __threadfence();                       // publish partials before the ticket
    __shared__ unsigned int s_ticket;
    if (t == 0) s_ticket = atomicAdd(&g_cnt[b], 1u);
    __syncthreads();
    if (s_ticket == NCHUNK - 1) {
        __threadfence();                   // acquire: other blocks' partials
        float L = 0.f;
        #pragma unroll
        for (int k = 0; k < NCHUNK; k++) L += g_pl[b * NCHUNK + k];
        float acc = 0.f;
        #pragma unroll 8
        for (int k = 0; k < NCHUNK; k++)
            acc += g_pacc[((size_t)b * NCHUNK + k) * DD + t];
        outp[b * DD + t] = acc / (L * (float)SS);
    }
}

// ---------------------------------------------------------------------------
extern "C" void kernel_launch(void* const* d_in, const int* in_sizes, int n_in,
                              void* d_out, int out_size) {
    const float* h   = (const float*)d_in[0];
    const float* q   = (const float*)d_in[1];
    const float* pf1 = (const float*)d_in[2];
    const float* pf2 = (const float*)d_in[3];
    const float* Wh  = (const float*)d_in[4];
    const float* Wq  = (const float*)d_in[5];
    const float* Wp1 = (const float*)d_in[6];
    const float* Wp2 = (const float*)d_in[7];
    const float* Wc  = (const float*)d_in[8];
    const float* bc  = (const float*)d_in[9];
    float* out = (float*)d_out;

    prep_kernel<<<40, 256>>>(Wh, Wq, Wp1, Wp2, Wc);
    score_kernel<<<dim3(NCHUNK, BB), 256>>>(h, pf1, pf2, q, bc, out);
}

// round 10
// speedup vs baseline: 1.7946x; 1.0154x over previous
#include <cuda_runtime.h>
#include <cuda_bf16.h>

// Problem constants
#define BB 32
#define SS 4096
#define DD 256
#define DA 128
#define DP 64

#define NCHUNK 16            // grid 512 = single wave @ occ 4
#define SPC (SS / NCHUNK)    // 256 s-rows per block
#define NWARP 8
#define SPW (SPC / NWARP)    // 32 s-rows per warp

#define DEPTH 3              // cp.async pipeline stages per warp
#define STAGE_BYTES 1536     // h 1024 + pf1 256 + pf2 256

// Scratch (allocation-free rule: __device__ globals)
__device__ float g_va[DD];
__device__ float g_wqv[DD];
__device__ float g_vp1[DP];
__device__ float g_vp2[DP];
__device__ float g_pl[BB * NCHUNK];
__device__ float g_pacc[BB * NCHUNK * DD];
__device__ unsigned int g_cnt[BB];

// ---------------------------------------------------------------------------
__device__ __forceinline__ void cp16(void* dst, const void* src) {
    unsigned int saddr = (unsigned int)__cvta_generic_to_shared(dst);
    asm volatile("cp.async.cg.shared.global [%0], [%1], 16;"
                 :: "r"(saddr), "l"(src) : "memory");
}
__device__ __forceinline__ void cp_commit() {
    asm volatile("cp.async.commit_group;" ::: "memory");
}
__device__ __forceinline__ void cp_wait1() {
    asm volatile("cp.async.wait_group 1;" ::: "memory");
}
__device__ __forceinline__ void cp_wait0() {
    asm volatile("cp.async.wait_group 0;" ::: "memory");
}

// ---------------------------------------------------------------------------
// Kernel 0: fold Wc into projection vectors; reset completion counters.
// ---------------------------------------------------------------------------
__global__ void prep_kernel(const float* __restrict__ Wh,
                            const float* __restrict__ Wq,
                            const float* __restrict__ Wp1,
                            const float* __restrict__ Wp2,
                            const float* __restrict__ Wc) {
    __shared__ float red[256];
    const int blk = blockIdx.x;
    const int t   = threadIdx.x;
    const int tl  = t & 15;
    const int ag  = t >> 4;

    if (blk == 0 && t < BB) g_cnt[t] = 0u;

    float acc = 0.f;
    float* out;
    int t0;

    if (blk < 32) {
        const float* W    = (blk < 16) ? Wh : Wq;
        const float* wvec = (blk < 16) ? Wc : (Wc + DA);
        out = (blk < 16) ? g_va : g_wqv;
        t0  = (blk & 15) * 16;
        #pragma unroll
        for (int k = 0; k < 8; k++) {
            int a = ag + k * 16;
            acc += W[a * DD + t0 + tl] * wvec[a];
        }
    } else {
        const float* W    = (blk < 36) ? Wp1 : Wp2;
        const float* wvec = (blk < 36) ? (Wc + 2 * DA) : (Wc + 2 * DA + DP);
        out = (blk < 36) ? g_vp1 : g_vp2;
        t0  = (blk & 3) * 16;
        #pragma unroll
        for (int k = 0; k < 4; k++) {
            int a = ag + k * 16;
            acc += W[a * DP + t0 + tl] * wvec[a];
        }
    }

    red[t] = acc;
    __syncthreads();
    if (t < 16) {
        float s = 0.f;
        #pragma unroll
        for (int g = 0; g < 16; g++) s += red[g * 16 + t];
        out[t0 + t] = s;
    }
}

// ---------------------------------------------------------------------------
// Kernel 1: fused score + tanh + exp + weighted accumulation with a per-warp
// cp.async 3-stage smem pipeline (register-free MLP: ~2 rows of h+pf in
// flight per warp at all times -> saturates HBM). Finalize folded in via
// per-batch atomic ticket.
// ---------------------------------------------------------------------------
__global__ void __launch_bounds__(256, 4)
score_kernel(const float* __restrict__ h,
             const float* __restrict__ pf1,
             const float* __restrict__ pf2,
             const float* __restrict__ q,
             const float* __restrict__ bc,
             float* __restrict__ outp) {
    const int b     = blockIdx.y;
    const int chunk = blockIdx.x;
    const int t     = threadIdx.x;
    const int w     = t >> 5;
    const int lane  = t & 31;

    __shared__ __align__(16) char s_pipe[NWARP][DEPTH][STAGE_BYTES];
    __shared__ float s_red[NWARP];
    __shared__ float s_acc[NWARP][DD];
    __shared__ float s_l[NWARP];
    __shared__ unsigned int s_ticket;

    const int s0 = chunk * SPC + w * SPW;
    const float* hrow = h   + ((size_t)b * SS + s0) * DD;
    const float* p1r  = pf1 + ((size_t)b * SS + s0) * DP;
    const float* p2r  = pf2 + ((size_t)b * SS + s0) * DP;

    // ---- pipeline prologue: issue rows 0 and 1 (stages 0,1) ----
    #pragma unroll
    for (int st = 0; st < 2; st++) {
        char* base = s_pipe[w][st];
        cp16(base + 16 * lane,        hrow + 4 * lane);
        cp16(base + 512 + 16 * lane,  hrow + 128 + 4 * lane);
        if (lane < 16) cp16(base + 1024 + 16 * lane,        p1r + 4 * lane);
        else           cp16(base + 1280 + 16 * (lane - 16), p2r + 4 * (lane - 16));
        cp_commit();
        hrow += DD; p1r += DP; p2r += DP;
    }

    // ---- cq[b] = q[b] . wqv + bc (overlaps with pipeline fill) ----
    {
        float p = g_wqv[t] * q[b * DD + t];
        #pragma unroll
        for (int off = 16; off; off >>= 1)
            p += __shfl_xor_sync(0xffffffffu, p, off);
        if (lane == 0) s_red[w] = p;
    }

    // Per-lane projection-vector slices (L2-resident)
    const float4 va0 = *(const float4*)(g_va + lane * 8);
    const float4 va1 = *(const float4*)(g_va + lane * 8 + 4);
    const float2 w1  = *(const float2*)(g_vp1 + lane * 2);
    const float2 w2  = *(const float2*)(g_vp2 + lane * 2);

    __syncthreads();
    float cqb = bc[0];
    #pragma unroll
    for (int ww = 0; ww < NWARP; ww++) cqb += s_red[ww];

    float l = 0.f;
    float a0 = 0.f, a1 = 0.f, a2 = 0.f, a3 = 0.f;
    float a4 = 0.f, a5 = 0.f, a6 = 0.f, a7 = 0.f;

    int st_proc = 0, st_issue = 2;

    #pragma unroll 2
    for (int i = 0; i < SPW; i++) {
        if (i + 1 < SPW) cp_wait1(); else cp_wait0();
        __syncwarp();   // all lanes' copies of row i complete; row i-1 reads done

        if (i + 2 < SPW) {
            char* base = s_pipe[w][st_issue];
            cp16(base + 16 * lane,        hrow + 4 * lane);
            cp16(base + 512 + 16 * lane,  hrow + 128 + 4 * lane);
            if (lane < 16) cp16(base + 1024 + 16 * lane,        p1r + 4 * lane);
            else           cp16(base + 1280 + 16 * (lane - 16), p2r + 4 * (lane - 16));
            cp_commit();
            hrow += DD; p1r += DP; p2r += DP;
            st_issue = (st_issue + 1 == DEPTH) ? 0 : st_issue + 1;
        }

        const char* base = s_pipe[w][st_proc];
        st_proc = (st_proc + 1 == DEPTH) ? 0 : st_proc + 1;
        const float4 h0 = ((const float4*)base)[2 * lane];
        const float4 h1 = ((const float4*)base)[2 * lane + 1];
        const float2 f1 = ((const float2*)(base + 1024))[lane];
        const float2 f2 = ((const float2*)(base + 1280))[lane];

        float part = h0.x * va0.x + h0.y * va0.y + h0.z * va0.z + h0.w * va0.w
                   + h1.x * va1.x + h1.y * va1.y + h1.z * va1.z + h1.w * va1.w
                   + f1.x * w1.x  + f1.y * w1.y
                   + f2.x * w2.x  + f2.y * w2.y;
        #pragma unroll
        for (int off = 16; off; off >>= 1)
            part += __shfl_xor_sync(0xffffffffu, part, off);

        // tanh bounded -> exp always safe, no running max needed
        const float wgt = __expf(tanhf(part + cqb));
        l  += wgt;
        a0 += wgt * h0.x;  a1 += wgt * h0.y;  a2 += wgt * h0.z;  a3 += wgt * h0.w;
        a4 += wgt * h1.x;  a5 += wgt * h1.y;  a6 += wgt * h1.z;  a7 += wgt * h1.w;
    }

    // ---- block-level combine of 8 warp partials ----
    float* dst = &s_acc[w][lane * 8];
    dst[0] = a0; dst[1] = a1; dst[2] = a2; dst[3] = a3;
    dst[4] = a4; dst[5] = a5; dst[6] = a6; dst[7] = a7;
    if (lane == 0) s_l[w] = l;
    __syncthreads();

    float accd = 0.f;
    #pragma unroll
    for (int ww = 0; ww < NWARP; ww++) accd += s_acc[ww][t];
    const int pidx = b * NCHUNK + chunk;
    g_pacc[(size_t)pidx * DD + t] = accd;
    if (t == 0) {
        float L = 0.f;
        #pragma unroll
        for (int ww = 0; ww < NWARP; ww++) L += s_l[ww];
        g_pl[pidx] = L;
    }

    // ---- inlined finalize: last block of this batch combines partials ----
    __threadfence();
    if (t == 0) s_ticket = atomicAdd(&g_cnt[b], 1u);
    __syncthreads();
    if (s_ticket == NCHUNK - 1) {
        __threadfence();
        float L = 0.f;
        #pragma unroll
        for (int k = 0; k < NCHUNK; k++) L += g_pl[b * NCHUNK + k];
        float acc = 0.f;
        #pragma unroll 8
        for (int k = 0; k < NCHUNK; k++)
            acc += g_pacc[((size_t)b * NCHUNK + k) * DD + t];
        outp[b * DD + t] = acc / (L * (float)SS);
    }
}

// ---------------------------------------------------------------------------
extern "C" void kernel_launch(void* const* d_in, const int* in_sizes, int n_in,
                              void* d_out, int out_size) {
    const float* h   = (const float*)d_in[0];
    const float* q   = (const float*)d_in[1];
    const float* pf1 = (const float*)d_in[2];
    const float* pf2 = (const float*)d_in[3];
    const float* Wh  = (const float*)d_in[4];
    const float* Wq  = (const float*)d_in[5];
    const float* Wp1 = (const float*)d_in[6];
    const float* Wp2 = (const float*)d_in[7];
    const float* Wc  = (const float*)d_in[8];
    const float* bc  = (const float*)d_in[9];
    float* out = (float*)d_out;

    prep_kernel<<<40, 256>>>(Wh, Wq, Wp1, Wp2, Wc);
    score_kernel<<<dim3(NCHUNK, BB), 256>>>(h, pf1, pf2, q, bc, out);
}